// round 1
// baseline (speedup 1.0000x reference)
#include <cuda_runtime.h>
#include <math.h>

#define NB   4096
#define NE   16
#define DI   1024
#define DH   2048
#define DOUT 1024
#define NSLOT (NB * 2)   // 8192 token-slots, always exactly this many

// ---------------- scratch (device globals; no allocation allowed) ----------
__device__ float g_h[NSLOT * DH];          // 64 MB: relu(x@w1^T + b1) per slot
__device__ float g_contrib[NSLOT * DOUT];  // 32 MB: weighted expert output per slot
__device__ int   g_perm[NSLOT];            // expert-sorted list of (token*2+slot)
__device__ int   g_inv[NSLOT];             // inverse permutation
__device__ int   g_counts[NE];
__device__ int   g_cursor[NE];
__device__ int   g_off[NE + 1];
__device__ int   g_tidx[NB * 2];           // top-2 expert ids
__device__ float g_tw[NB * 2];             // softmax gate weights

// ---------------- init: zero counters (runs every replay) ------------------
__global__ void init_kernel() {
    int t = threadIdx.x;
    if (t < NE) { g_counts[t] = 0; g_cursor[t] = 0; }
}

// ---------------- gate: scores, top-2, softmax, counts ---------------------
// 4 tokens per block, 128 threads. gate_w (64KB) stays hot in L2/L1.
__global__ __launch_bounds__(128) void gate_kernel(const float* __restrict__ x,
                                                   const float* __restrict__ gw) {
    __shared__ float xs[4][DI];
    __shared__ float sc[4][NE];
    int t0 = blockIdx.x * 4;

    const float4* xsrc = (const float4*)(x + (size_t)t0 * DI);
    float4* xd = (float4*)&xs[0][0];
    #pragma unroll 4
    for (int i = threadIdx.x; i < 4 * DI / 4; i += 128) xd[i] = xsrc[i];
    __syncthreads();

    int warp = threadIdx.x >> 5, lane = threadIdx.x & 31;
    for (int e = warp * 4; e < warp * 4 + 4; ++e) {
        float s0 = 0.f, s1 = 0.f, s2 = 0.f, s3 = 0.f;
        for (int i = lane; i < DI; i += 32) {
            float g = gw[e * DI + i];
            s0 += xs[0][i] * g; s1 += xs[1][i] * g;
            s2 += xs[2][i] * g; s3 += xs[3][i] * g;
        }
        #pragma unroll
        for (int o = 16; o > 0; o >>= 1) {
            s0 += __shfl_xor_sync(0xffffffffu, s0, o);
            s1 += __shfl_xor_sync(0xffffffffu, s1, o);
            s2 += __shfl_xor_sync(0xffffffffu, s2, o);
            s3 += __shfl_xor_sync(0xffffffffu, s3, o);
        }
        if (lane == 0) { sc[0][e] = s0; sc[1][e] = s1; sc[2][e] = s2; sc[3][e] = s3; }
    }
    __syncthreads();

    if (threadIdx.x < 4) {
        int tt = threadIdx.x;
        int tok = t0 + tt;
        float bv = -1e30f; int bi = 0;
        #pragma unroll
        for (int e = 0; e < NE; ++e) {
            float v = sc[tt][e];
            if (v > bv) { bv = v; bi = e; }
        }
        float bv2 = -1e30f; int bi2 = 0;
        #pragma unroll
        for (int e = 0; e < NE; ++e) {
            if (e == bi) continue;
            float v = sc[tt][e];
            if (v > bv2) { bv2 = v; bi2 = e; }
        }
        float e2 = expf(bv2 - bv);       // softmax over [bv, bv2]
        float inv = 1.0f / (1.0f + e2);
        g_tidx[tok * 2 + 0] = bi;  g_tw[tok * 2 + 0] = inv;
        g_tidx[tok * 2 + 1] = bi2; g_tw[tok * 2 + 1] = e2 * inv;
        atomicAdd(&g_counts[bi], 1);
        atomicAdd(&g_counts[bi2], 1);
    }
}

// ---------------- prefix sum over 16 experts --------------------------------
__global__ void prefix_kernel() {
    if (threadIdx.x == 0) {
        int s = 0;
        #pragma unroll
        for (int e = 0; e < NE; ++e) { g_off[e] = s; s += g_counts[e]; }
        g_off[NE] = s;   // always 8192
    }
}

// ---------------- scatter: build perm / inv ---------------------------------
__global__ __launch_bounds__(256) void scatter_kernel() {
    int tok = blockIdx.x * 256 + threadIdx.x;
    if (tok >= NB) return;
    #pragma unroll
    for (int slot = 0; slot < 2; ++slot) {
        int pair = tok * 2 + slot;
        int e = g_tidx[pair];
        int pos = g_off[e] + atomicAdd(&g_cursor[e], 1);
        g_perm[pos] = pair;
        g_inv[pair] = pos;
    }
}

// ---------------- grouped SGEMM: 64x64 tile, BK=16, double-buffered ---------
// MODE 0: C[m] = relu( x[token(m)] @ w1[e]^T + b1[e] )      (K=DI,  N=DH)
// MODE 1: C[m] = ( g_h[m] @ w2[e]^T + b2[e] ) * gate_w(m)   (K=DH,  N=DOUT)
template <int K, int NTOT, int MODE>
__global__ __launch_bounds__(256) void gemm_kernel(const float* __restrict__ Ap,
                                                   const float* __restrict__ W,
                                                   const float* __restrict__ bias) {
    __shared__ float as[2][16][64];
    __shared__ float bs[2][16][64];

    int e = blockIdx.z;
    int mStart = g_off[e], mEnd = g_off[e + 1];
    int m0 = mStart + blockIdx.y * 64;
    if (m0 >= mEnd) return;
    int n0 = blockIdx.x * 64;

    const float* A = (MODE == 0) ? Ap : g_h;
    float* C = (MODE == 0) ? g_h : g_contrib;

    int tid = threadIdx.x;
    int ldRow = tid >> 2;            // 0..63
    int ldK = (tid & 3) * 4;         // 0,4,8,12

    int gRow = m0 + ldRow;
    bool aValid = (gRow < mEnd);
    const float* aPtr;
    if (MODE == 0) {
        int pair = aValid ? g_perm[gRow] : 0;
        aPtr = A + (size_t)(pair >> 1) * K + ldK;
    } else {
        aPtr = A + (size_t)(aValid ? gRow : m0) * K + ldK;
    }
    const float* bPtr = W + (size_t)e * NTOT * K + (size_t)(n0 + ldRow) * K + ldK;

    int tx = tid & 15, ty = tid >> 4;
    float acc[4][4];
    #pragma unroll
    for (int i = 0; i < 4; ++i)
        #pragma unroll
        for (int j = 0; j < 4; ++j) acc[i][j] = 0.f;

    const int NSTAGE = K / 16;
    float4 pa, pb;

    pa = aValid ? *(const float4*)(aPtr) : make_float4(0.f, 0.f, 0.f, 0.f);
    pb = *(const float4*)(bPtr);
    as[0][ldK + 0][ldRow] = pa.x; as[0][ldK + 1][ldRow] = pa.y;
    as[0][ldK + 2][ldRow] = pa.z; as[0][ldK + 3][ldRow] = pa.w;
    bs[0][ldK + 0][ldRow] = pb.x; bs[0][ldK + 1][ldRow] = pb.y;
    bs[0][ldK + 2][ldRow] = pb.z; bs[0][ldK + 3][ldRow] = pb.w;
    __syncthreads();

    for (int s = 0; s < NSTAGE; ++s) {
        if (s + 1 < NSTAGE) {
            pa = aValid ? *(const float4*)(aPtr + (s + 1) * 16)
                        : make_float4(0.f, 0.f, 0.f, 0.f);
            pb = *(const float4*)(bPtr + (s + 1) * 16);
        }
        int buf = s & 1;
        #pragma unroll
        for (int kk = 0; kk < 16; ++kk) {
            float4 av = *(const float4*)&as[buf][kk][ty * 4];
            float4 bv = *(const float4*)&bs[buf][kk][tx * 4];
            acc[0][0] += av.x * bv.x; acc[0][1] += av.x * bv.y;
            acc[0][2] += av.x * bv.z; acc[0][3] += av.x * bv.w;
            acc[1][0] += av.y * bv.x; acc[1][1] += av.y * bv.y;
            acc[1][2] += av.y * bv.z; acc[1][3] += av.y * bv.w;
            acc[2][0] += av.z * bv.x; acc[2][1] += av.z * bv.y;
            acc[2][2] += av.z * bv.z; acc[2][3] += av.z * bv.w;
            acc[3][0] += av.w * bv.x; acc[3][1] += av.w * bv.y;
            acc[3][2] += av.w * bv.z; acc[3][3] += av.w * bv.w;
        }
        if (s + 1 < NSTAGE) {
            int nb = (s + 1) & 1;
            as[nb][ldK + 0][ldRow] = pa.x; as[nb][ldK + 1][ldRow] = pa.y;
            as[nb][ldK + 2][ldRow] = pa.z; as[nb][ldK + 3][ldRow] = pa.w;
            bs[nb][ldK + 0][ldRow] = pb.x; bs[nb][ldK + 1][ldRow] = pb.y;
            bs[nb][ldK + 2][ldRow] = pb.z; bs[nb][ldK + 3][ldRow] = pb.w;
        }
        __syncthreads();
    }

    // epilogue
    #pragma unroll
    for (int mi = 0; mi < 4; ++mi) {
        int row = m0 + ty * 4 + mi;
        if (row < mEnd) {
            int n = n0 + tx * 4;
            float wsc = 1.f;
            if (MODE == 1) wsc = g_tw[g_perm[row]];
            float4 o;
            o.x = acc[mi][0] + bias[e * NTOT + n + 0];
            o.y = acc[mi][1] + bias[e * NTOT + n + 1];
            o.z = acc[mi][2] + bias[e * NTOT + n + 2];
            o.w = acc[mi][3] + bias[e * NTOT + n + 3];
            if (MODE == 0) {
                o.x = fmaxf(o.x, 0.f); o.y = fmaxf(o.y, 0.f);
                o.z = fmaxf(o.z, 0.f); o.w = fmaxf(o.w, 0.f);
            } else {
                o.x *= wsc; o.y *= wsc; o.z *= wsc; o.w *= wsc;
            }
            *(float4*)&C[(size_t)row * NTOT + n] = o;
        }
    }
}

// ---------------- combine: out[t] = contrib[slot0] + contrib[slot1] ---------
__global__ __launch_bounds__(256) void combine_kernel(float* __restrict__ out) {
    int idx = blockIdx.x * 256 + threadIdx.x;   // over NB * (DOUT/4)
    int tok = idx >> 8;
    int d4 = idx & 255;
    const float4* c0 = (const float4*)&g_contrib[(size_t)g_inv[tok * 2 + 0] * DOUT];
    const float4* c1 = (const float4*)&g_contrib[(size_t)g_inv[tok * 2 + 1] * DOUT];
    float4 a = c0[d4], b = c1[d4];
    float4 r;
    r.x = a.x + b.x; r.y = a.y + b.y; r.z = a.z + b.z; r.w = a.w + b.w;
    ((float4*)out)[idx] = r;
}

// ---------------- launch -----------------------------------------------------
extern "C" void kernel_launch(void* const* d_in, const int* in_sizes, int n_in,
                              void* d_out, int out_size) {
    const float* x  = (const float*)d_in[0];
    const float* gw = (const float*)d_in[1];
    const float* w1 = (const float*)d_in[2];
    const float* b1 = (const float*)d_in[3];
    const float* w2 = (const float*)d_in[4];
    const float* b2 = (const float*)d_in[5];
    float* out = (float*)d_out;

    init_kernel<<<1, 32>>>();
    gate_kernel<<<NB / 4, 128>>>(x, gw);
    prefix_kernel<<<1, 32>>>();
    scatter_kernel<<<(NB + 255) / 256, 256>>>();
    // GEMM1: rows = 8192 slots, N=2048, K=1024 (worst case one expert owns all rows)
    gemm_kernel<DI, DH, 0><<<dim3(DH / 64, NSLOT / 64, NE), 256>>>(x, w1, b1);
    // GEMM2: rows = 8192 slots, N=1024, K=2048
    gemm_kernel<DH, DOUT, 1><<<dim3(DOUT / 64, NSLOT / 64, NE), 256>>>(nullptr, w2, b2);
    combine_kernel<<<NB * (DOUT / 4) / 256, 256>>>(out);
}

// round 3
// speedup vs baseline: 4.2125x; 4.2125x over previous
#include <cuda_runtime.h>
#include <math.h>
#include <stdint.h>

#define NB   4096
#define NE   16
#define DI   1024
#define DH   2048
#define DOUT 1024
#define NSLOT (NB * 2)

// ---------------- scratch ----------------------------------------------------
__device__ float g_h[(size_t)NSLOT * DH];
__device__ float g_contrib[(size_t)NSLOT * DOUT];
__device__ int   g_perm[NSLOT];
__device__ int   g_inv[NSLOT];
__device__ int   g_counts[NE];
__device__ int   g_cursor[NE];
__device__ int   g_off[NE + 1];
__device__ int   g_tidx[NB * 2];
__device__ float g_tw[NB * 2];

// ---------------- helpers ----------------------------------------------------
__device__ __forceinline__ uint32_t f2tf32(float f) {
    uint32_t u; asm("cvt.rna.tf32.f32 %0, %1;" : "=r"(u) : "f"(f)); return u;
}
__device__ __forceinline__ void ldsm4(uint32_t addr, uint32_t* a) {
    asm volatile("ldmatrix.sync.aligned.m8n8.x4.shared.b16 {%0,%1,%2,%3}, [%4];"
                 : "=r"(a[0]), "=r"(a[1]), "=r"(a[2]), "=r"(a[3]) : "r"(addr));
}
__device__ __forceinline__ void mma_tf32(float* d, const uint32_t* a, const uint32_t* b) {
    asm volatile(
        "mma.sync.aligned.m16n8k8.row.col.f32.tf32.tf32.f32 "
        "{%0,%1,%2,%3}, {%4,%5,%6,%7}, {%8,%9}, {%0,%1,%2,%3};"
        : "+f"(d[0]), "+f"(d[1]), "+f"(d[2]), "+f"(d[3])
        : "r"(a[0]), "r"(a[1]), "r"(a[2]), "r"(a[3]), "r"(b[0]), "r"(b[1]));
}

// ---------------- init -------------------------------------------------------
__global__ void init_kernel() {
    int t = threadIdx.x;
    if (t < NE) { g_counts[t] = 0; g_cursor[t] = 0; }
}

// ---------------- gate (fp32 exact — routing must match reference) -----------
__global__ __launch_bounds__(128) void gate_kernel(const float* __restrict__ x,
                                                   const float* __restrict__ gw) {
    __shared__ float xs[4][DI];
    __shared__ float sc[4][NE];
    int t0 = blockIdx.x * 4;

    const float4* xsrc = (const float4*)(x + (size_t)t0 * DI);
    float4* xd = (float4*)&xs[0][0];
    #pragma unroll 4
    for (int i = threadIdx.x; i < 4 * DI / 4; i += 128) xd[i] = xsrc[i];
    __syncthreads();

    int warp = threadIdx.x >> 5, lane = threadIdx.x & 31;
    for (int e = warp * 4; e < warp * 4 + 4; ++e) {
        float s0 = 0.f, s1 = 0.f, s2 = 0.f, s3 = 0.f;
        for (int i = lane; i < DI; i += 32) {
            float g = gw[e * DI + i];
            s0 += xs[0][i] * g; s1 += xs[1][i] * g;
            s2 += xs[2][i] * g; s3 += xs[3][i] * g;
        }
        #pragma unroll
        for (int o = 16; o > 0; o >>= 1) {
            s0 += __shfl_xor_sync(0xffffffffu, s0, o);
            s1 += __shfl_xor_sync(0xffffffffu, s1, o);
            s2 += __shfl_xor_sync(0xffffffffu, s2, o);
            s3 += __shfl_xor_sync(0xffffffffu, s3, o);
        }
        if (lane == 0) { sc[0][e] = s0; sc[1][e] = s1; sc[2][e] = s2; sc[3][e] = s3; }
    }
    __syncthreads();

    if (threadIdx.x < 4) {
        int tt = threadIdx.x;
        int tok = t0 + tt;
        float bv = -1e30f; int bi = 0;
        #pragma unroll
        for (int e = 0; e < NE; ++e) {
            float v = sc[tt][e];
            if (v > bv) { bv = v; bi = e; }
        }
        float bv2 = -1e30f; int bi2 = 0;
        #pragma unroll
        for (int e = 0; e < NE; ++e) {
            if (e == bi) continue;
            float v = sc[tt][e];
            if (v > bv2) { bv2 = v; bi2 = e; }
        }
        float e2 = expf(bv2 - bv);
        float inv = 1.0f / (1.0f + e2);
        g_tidx[tok * 2 + 0] = bi;  g_tw[tok * 2 + 0] = inv;
        g_tidx[tok * 2 + 1] = bi2; g_tw[tok * 2 + 1] = e2 * inv;
        atomicAdd(&g_counts[bi], 1);
        atomicAdd(&g_counts[bi2], 1);
    }
}

// ---------------- prefix -----------------------------------------------------
__global__ void prefix_kernel() {
    if (threadIdx.x == 0) {
        int s = 0;
        #pragma unroll
        for (int e = 0; e < NE; ++e) { g_off[e] = s; s += g_counts[e]; }
        g_off[NE] = s;
    }
}

// ---------------- scatter ----------------------------------------------------
__global__ __launch_bounds__(256) void scatter_kernel() {
    int tok = blockIdx.x * 256 + threadIdx.x;
    if (tok >= NB) return;
    #pragma unroll
    for (int slot = 0; slot < 2; ++slot) {
        int pair = tok * 2 + slot;
        int e = g_tidx[pair];
        int pos = g_off[e] + atomicAdd(&g_cursor[e], 1);
        g_perm[pos] = pair;
        g_inv[pair] = pos;
    }
}

// ---------------- mma.sync tf32 grouped GEMM --------------------------------
// CTA tile 128x128, BK=32. A m-major / B n-major in smem, stride 36 floats
// (conflict-free tf32 fragment banks). A frags via ldmatrix.x4 (b16 view).
// MODE 0: C = relu(gather(x) @ w1^T + b1)  -> g_h       (K=DI,  NTOT=DH)
// MODE 1: C = (g_h @ w2^T + b2) * gate_w   -> g_contrib (K=DH,  NTOT=DOUT)
#define TSTRIDE 36
#define ABUF (128 * TSTRIDE)        // floats per tile
#define BUFS (2 * ABUF)             // floats per stage (A + B)
#define GEMM_SMEM (2 * BUFS * 4)    // bytes, double-buffered = 73728

template <int K, int NTOT, int MODE>
__global__ __launch_bounds__(256) void gemm_tc(const float* __restrict__ Ap,
                                               const float* __restrict__ W,
                                               const float* __restrict__ bias) {
    extern __shared__ float smf[];
    __shared__ float bias_s[128];
    const int NC = K / 32;

    int e = blockIdx.z;
    int mStart = g_off[e], mEnd = g_off[e + 1];
    int m0 = mStart + blockIdx.y * 128;
    if (m0 >= mEnd) return;
    int n0 = blockIdx.x * 128;

    int tid = threadIdx.x, lane = tid & 31, wid = tid >> 5;
    int mw = (wid >> 2) * 64;      // warp m offset (2 warps in m)
    int nw = (wid & 3) * 32;       // warp n offset (4 warps in n)

    if (tid < 128) bias_s[tid] = bias[e * NTOT + n0 + tid];

    // ---- loader mapping: row = (tid>>3)+32*i  (0..127), c4 = tid&7 (float4 col)
    int lrow = tid >> 3;
    int c4 = tid & 7;
    const float* aP[4];
    const float* bP[4];
    int stsOff[4];
    #pragma unroll
    for (int i = 0; i < 4; ++i) {
        int row = lrow + 32 * i;
        int gRow = m0 + row;
        int cRow = (gRow < mEnd) ? gRow : mStart;   // clamp (values unused if OOB)
        if (MODE == 0) {
            int pair = g_perm[cRow];
            aP[i] = Ap + (size_t)(pair >> 1) * K + c4 * 4;
        } else {
            aP[i] = g_h + (size_t)cRow * K + c4 * 4;
        }
        bP[i] = W + (size_t)e * NTOT * K + (size_t)(n0 + row) * K + c4 * 4;
        stsOff[i] = row * TSTRIDE + c4 * 4;
    }

    // fragment addressing
    uint32_t smemBase = (uint32_t)__cvta_generic_to_shared(smf);
    uint32_t aAddrBase = smemBase +
        (uint32_t)(((mw + (lane & 15)) * TSTRIDE + (lane >> 4) * 4) * 4);
    int bIdxBase = ABUF + (nw + (lane >> 2)) * TSTRIDE + (lane & 3);

    float acc[4][4][4];
    #pragma unroll
    for (int mi = 0; mi < 4; ++mi)
        #pragma unroll
        for (int ni = 0; ni < 4; ++ni)
            #pragma unroll
            for (int j = 0; j < 4; ++j) acc[mi][ni][j] = 0.f;

    float4 pa[4], pb[4];
    #pragma unroll
    for (int i = 0; i < 4; ++i) { pa[i] = *(const float4*)(aP[i]); pb[i] = *(const float4*)(bP[i]); }
    // store chunk 0 -> buffer 0 (tf32 rna convert)
    #pragma unroll
    for (int i = 0; i < 4; ++i) {
        uint4 u;
        u.x = f2tf32(pa[i].x); u.y = f2tf32(pa[i].y); u.z = f2tf32(pa[i].z); u.w = f2tf32(pa[i].w);
        *(uint4*)(smf + stsOff[i]) = u;
        u.x = f2tf32(pb[i].x); u.y = f2tf32(pb[i].y); u.z = f2tf32(pb[i].z); u.w = f2tf32(pb[i].w);
        *(uint4*)(smf + ABUF + stsOff[i]) = u;
    }
    __syncthreads();

    for (int s = 0; s < NC; ++s) {
        int b = s & 1;
        if (s + 1 < NC) {
            #pragma unroll
            for (int i = 0; i < 4; ++i) {
                pa[i] = *(const float4*)(aP[i] + (s + 1) * 32);
                pb[i] = *(const float4*)(bP[i] + (s + 1) * 32);
            }
        }
        // ---- compute on buffer b
        uint32_t aAddr = aAddrBase + (uint32_t)(b * BUFS * 4);
        int bIdx = b * BUFS + bIdxBase;
        #pragma unroll
        for (int ks = 0; ks < 4; ++ks) {
            uint32_t af[4][4];
            #pragma unroll
            for (int mi = 0; mi < 4; ++mi)
                ldsm4(aAddr + mi * (16 * TSTRIDE * 4) + ks * 32, af[mi]);
            uint32_t bf[4][2];
            #pragma unroll
            for (int ni = 0; ni < 4; ++ni) {
                int idx = bIdx + ni * 8 * TSTRIDE + ks * 8;
                bf[ni][0] = __float_as_uint(smf[idx]);
                bf[ni][1] = __float_as_uint(smf[idx + 4]);
            }
            #pragma unroll
            for (int mi = 0; mi < 4; ++mi)
                #pragma unroll
                for (int ni = 0; ni < 4; ++ni)
                    mma_tf32(acc[mi][ni], af[mi], bf[ni]);
        }
        if (s + 1 < NC) {
            int nb = b ^ 1;
            #pragma unroll
            for (int i = 0; i < 4; ++i) {
                uint4 u;
                u.x = f2tf32(pa[i].x); u.y = f2tf32(pa[i].y); u.z = f2tf32(pa[i].z); u.w = f2tf32(pa[i].w);
                *(uint4*)(smf + nb * BUFS + stsOff[i]) = u;
                u.x = f2tf32(pb[i].x); u.y = f2tf32(pb[i].y); u.z = f2tf32(pb[i].z); u.w = f2tf32(pb[i].w);
                *(uint4*)(smf + nb * BUFS + ABUF + stsOff[i]) = u;
            }
            __syncthreads();
        }
    }

    // ---- epilogue
    float* Cb = (MODE == 0) ? g_h : g_contrib;
    int r4 = lane >> 2, cc = (lane & 3) * 2;
    #pragma unroll
    for (int mi = 0; mi < 4; ++mi) {
        int row0 = m0 + mw + mi * 16 + r4;
        int row1 = row0 + 8;
        bool v0 = row0 < mEnd, v1 = row1 < mEnd;
        float w0 = 1.f, w1 = 1.f;
        if (MODE == 1) {
            if (v0) w0 = g_tw[g_perm[row0]];
            if (v1) w1 = g_tw[g_perm[row1]];
        }
        float* C0 = Cb + (size_t)row0 * NTOT + n0;
        float* C1 = Cb + (size_t)row1 * NTOT + n0;
        #pragma unroll
        for (int ni = 0; ni < 4; ++ni) {
            int col = nw + ni * 8 + cc;
            float bb0 = bias_s[col], bb1 = bias_s[col + 1];
            const float* d = acc[mi][ni];
            if (MODE == 0) {
                if (v0) {
                    float2 o; o.x = fmaxf(d[0] + bb0, 0.f); o.y = fmaxf(d[1] + bb1, 0.f);
                    *(float2*)&C0[col] = o;
                }
                if (v1) {
                    float2 o; o.x = fmaxf(d[2] + bb0, 0.f); o.y = fmaxf(d[3] + bb1, 0.f);
                    *(float2*)&C1[col] = o;
                }
            } else {
                if (v0) {
                    float2 o; o.x = (d[0] + bb0) * w0; o.y = (d[1] + bb1) * w0;
                    *(float2*)&C0[col] = o;
                }
                if (v1) {
                    float2 o; o.x = (d[2] + bb0) * w1; o.y = (d[3] + bb1) * w1;
                    *(float2*)&C1[col] = o;
                }
            }
        }
    }
}

// ---------------- combine ----------------------------------------------------
__global__ __launch_bounds__(256) void combine_kernel(float* __restrict__ out) {
    int idx = blockIdx.x * 256 + threadIdx.x;
    int tok = idx >> 8;
    int d4 = idx & 255;
    const float4* c0 = (const float4*)&g_contrib[(size_t)g_inv[tok * 2 + 0] * DOUT];
    const float4* c1 = (const float4*)&g_contrib[(size_t)g_inv[tok * 2 + 1] * DOUT];
    float4 a = c0[d4], b = c1[d4];
    float4 r;
    r.x = a.x + b.x; r.y = a.y + b.y; r.z = a.z + b.z; r.w = a.w + b.w;
    ((float4*)out)[idx] = r;
}

// ---------------- launch -----------------------------------------------------
extern "C" void kernel_launch(void* const* d_in, const int* in_sizes, int n_in,
                              void* d_out, int out_size) {
    const float* x  = (const float*)d_in[0];
    const float* gw = (const float*)d_in[1];
    const float* w1 = (const float*)d_in[2];
    const float* b1 = (const float*)d_in[3];
    const float* w2 = (const float*)d_in[4];
    const float* b2 = (const float*)d_in[5];
    float* out = (float*)d_out;

    cudaFuncSetAttribute(gemm_tc<DI, DH, 0>,
                         cudaFuncAttributeMaxDynamicSharedMemorySize, GEMM_SMEM);
    cudaFuncSetAttribute(gemm_tc<DH, DOUT, 1>,
                         cudaFuncAttributeMaxDynamicSharedMemorySize, GEMM_SMEM);

    init_kernel<<<1, 32>>>();
    gate_kernel<<<NB / 4, 128>>>(x, gw);
    prefix_kernel<<<1, 32>>>();
    scatter_kernel<<<(NB + 255) / 256, 256>>>();
    gemm_tc<DI, DH, 0><<<dim3(DH / 128, NSLOT / 128, NE), 256, GEMM_SMEM>>>(x, w1, b1);
    gemm_tc<DH, DOUT, 1><<<dim3(DOUT / 128, NSLOT / 128, NE), 256, GEMM_SMEM>>>(nullptr, w2, b2);
    combine_kernel<<<NB * (DOUT / 4) / 256, 256>>>(out);
}

// round 4
// speedup vs baseline: 6.2387x; 1.4810x over previous
#include <cuda_runtime.h>
#include <cuda_fp16.h>
#include <math.h>
#include <stdint.h>

#define NB   4096
#define NE   16
#define DI   1024
#define DH   2048
#define DOUT 1024
#define NSLOT (NB * 2)

// ---------------- scratch ----------------------------------------------------
__device__ __half g_h[(size_t)NSLOT * DH];         // fp16 hidden activations
__device__ float  g_contrib[(size_t)NSLOT * DOUT];
__device__ int    g_perm[NSLOT];
__device__ int    g_inv[NSLOT];
__device__ int    g_counts[NE];
__device__ int    g_cursor[NE];
__device__ int    g_off[NE + 1];
__device__ int    g_tidx[NB * 2];
__device__ float  g_tw[NB * 2];

// ---------------- helpers ----------------------------------------------------
__device__ __forceinline__ void ldsm4(uint32_t addr, uint32_t* a) {
    asm volatile("ldmatrix.sync.aligned.m8n8.x4.shared.b16 {%0,%1,%2,%3}, [%4];"
                 : "=r"(a[0]), "=r"(a[1]), "=r"(a[2]), "=r"(a[3]) : "r"(addr));
}
__device__ __forceinline__ void mma_f16(float* d, const uint32_t* a, const uint32_t* b) {
    asm volatile(
        "mma.sync.aligned.m16n8k16.row.col.f32.f16.f16.f32 "
        "{%0,%1,%2,%3}, {%4,%5,%6,%7}, {%8,%9}, {%0,%1,%2,%3};"
        : "+f"(d[0]), "+f"(d[1]), "+f"(d[2]), "+f"(d[3])
        : "r"(a[0]), "r"(a[1]), "r"(a[2]), "r"(a[3]), "r"(b[0]), "r"(b[1]));
}
__device__ __forceinline__ uint32_t h2bits(__half2 h) {
    return *reinterpret_cast<uint32_t*>(&h);
}

// ---------------- init -------------------------------------------------------
__global__ void init_kernel() {
    int t = threadIdx.x;
    if (t < NE) { g_counts[t] = 0; g_cursor[t] = 0; }
}

// ---------------- gate (fp32 exact — routing must match reference) -----------
__global__ __launch_bounds__(128) void gate_kernel(const float* __restrict__ x,
                                                   const float* __restrict__ gw) {
    __shared__ float xs[4][DI];
    __shared__ float sc[4][NE];
    int t0 = blockIdx.x * 4;

    const float4* xsrc = (const float4*)(x + (size_t)t0 * DI);
    float4* xd = (float4*)&xs[0][0];
    #pragma unroll 4
    for (int i = threadIdx.x; i < 4 * DI / 4; i += 128) xd[i] = xsrc[i];
    __syncthreads();

    int warp = threadIdx.x >> 5, lane = threadIdx.x & 31;
    for (int e = warp * 4; e < warp * 4 + 4; ++e) {
        float s0 = 0.f, s1 = 0.f, s2 = 0.f, s3 = 0.f;
        for (int i = lane; i < DI; i += 32) {
            float g = gw[e * DI + i];
            s0 += xs[0][i] * g; s1 += xs[1][i] * g;
            s2 += xs[2][i] * g; s3 += xs[3][i] * g;
        }
        #pragma unroll
        for (int o = 16; o > 0; o >>= 1) {
            s0 += __shfl_xor_sync(0xffffffffu, s0, o);
            s1 += __shfl_xor_sync(0xffffffffu, s1, o);
            s2 += __shfl_xor_sync(0xffffffffu, s2, o);
            s3 += __shfl_xor_sync(0xffffffffu, s3, o);
        }
        if (lane == 0) { sc[0][e] = s0; sc[1][e] = s1; sc[2][e] = s2; sc[3][e] = s3; }
    }
    __syncthreads();

    if (threadIdx.x < 4) {
        int tt = threadIdx.x;
        int tok = t0 + tt;
        float bv = -1e30f; int bi = 0;
        #pragma unroll
        for (int e = 0; e < NE; ++e) {
            float v = sc[tt][e];
            if (v > bv) { bv = v; bi = e; }
        }
        float bv2 = -1e30f; int bi2 = 0;
        #pragma unroll
        for (int e = 0; e < NE; ++e) {
            if (e == bi) continue;
            float v = sc[tt][e];
            if (v > bv2) { bv2 = v; bi2 = e; }
        }
        float e2 = expf(bv2 - bv);
        float inv = 1.0f / (1.0f + e2);
        g_tidx[tok * 2 + 0] = bi;  g_tw[tok * 2 + 0] = inv;
        g_tidx[tok * 2 + 1] = bi2; g_tw[tok * 2 + 1] = e2 * inv;
        atomicAdd(&g_counts[bi], 1);
        atomicAdd(&g_counts[bi2], 1);
    }
}

// ---------------- prefix -----------------------------------------------------
__global__ void prefix_kernel() {
    if (threadIdx.x == 0) {
        int s = 0;
        #pragma unroll
        for (int e = 0; e < NE; ++e) { g_off[e] = s; s += g_counts[e]; }
        g_off[NE] = s;
    }
}

// ---------------- scatter ----------------------------------------------------
__global__ __launch_bounds__(256) void scatter_kernel() {
    int tok = blockIdx.x * 256 + threadIdx.x;
    if (tok >= NB) return;
    #pragma unroll
    for (int slot = 0; slot < 2; ++slot) {
        int pair = tok * 2 + slot;
        int e = g_tidx[pair];
        int pos = g_off[e] + atomicAdd(&g_cursor[e], 1);
        g_perm[pos] = pair;
        g_inv[pair] = pos;
    }
}

// ---------------- fp16 mma.sync grouped GEMM --------------------------------
// CTA tile 128x128, BK=32 halfs, double-buffered. A m-major / B n-major in
// smem, stride 40 halfs (80B rows -> conflict-free ldmatrix).
// MODE 0: g_h = relu(gather(x) @ w1^T + b1)        (K=DI,  NTOT=DH, A fp32)
// MODE 1: g_contrib = (g_h @ w2^T + b2) * gate_w   (K=DH,  NTOT=DOUT, A fp16)
#define TS 40
#define ABUF_H (128 * TS)          // halfs per tile (5120)
#define STAGE_H (2 * ABUF_H)       // halfs per stage (A+B)
#define GEMM_SMEM (2 * STAGE_H * 2)  // 40960 bytes

template <int K, int NTOT, int MODE>
__global__ __launch_bounds__(256) void gemm_tc(const float* __restrict__ Ap,
                                               const float* __restrict__ W,
                                               const float* __restrict__ bias) {
    extern __shared__ __half smh[];
    __shared__ float bias_s[128];
    const int NC = K / 32;

    int e = blockIdx.z;
    int mStart = g_off[e], mEnd = g_off[e + 1];
    int m0 = mStart + blockIdx.y * 128;
    if (m0 >= mEnd) return;
    int n0 = blockIdx.x * 128;

    int tid = threadIdx.x, lane = tid & 31, wid = tid >> 5;
    int mw = (wid >> 2) * 64;
    int nw = (wid & 3) * 32;

    if (tid < 128) bias_s[tid] = bias[e * NTOT + n0 + tid];

    // ---- B loader (fp32 weights): row = tid>>3 + 32*i, c4 = tid&7
    int brow = tid >> 3, bc4 = tid & 7;
    const float* bP[4];
    int bOff[4];
    #pragma unroll
    for (int i = 0; i < 4; ++i) {
        int row = brow + 32 * i;
        bP[i] = W + (size_t)e * NTOT * K + (size_t)(n0 + row) * K + bc4 * 4;
        bOff[i] = row * TS + bc4 * 4;
    }

    // ---- A loader
    const float* aP[4];        // MODE 0 (fp32 gather)
    const __half* aPh[2];      // MODE 1 (fp16 copy)
    int aOff[4], aOffH[2];
    if (MODE == 0) {
        #pragma unroll
        for (int i = 0; i < 4; ++i) {
            int row = brow + 32 * i;
            int gRow = m0 + row;
            int cRow = (gRow < mEnd) ? gRow : mStart;
            int pair = g_perm[cRow];
            aP[i] = Ap + (size_t)(pair >> 1) * K + bc4 * 4;
            aOff[i] = row * TS + bc4 * 4;
        }
    } else {
        int arow = tid >> 2, aseg = tid & 3;
        #pragma unroll
        for (int i = 0; i < 2; ++i) {
            int row = arow + 64 * i;
            int gRow = m0 + row;
            int cRow = (gRow < mEnd) ? gRow : mStart;
            aPh[i] = g_h + (size_t)cRow * K + aseg * 8;
            aOffH[i] = row * TS + aseg * 8;
        }
    }

    // ---- fragment addressing
    uint32_t sb = (uint32_t)__cvta_generic_to_shared(smh);
    uint32_t aAddrBase = sb + (uint32_t)(((mw + (lane & 15)) * TS + (lane >> 4) * 8) * 2);
    int bg = lane >> 3;                 // 0..3
    int nblk = bg >> 1, khalf = bg & 1;
    uint32_t bAddrBase = sb + (uint32_t)((ABUF_H +
        (nw + nblk * 8 + (lane & 7)) * TS + khalf * 8) * 2);

    float acc[4][4][4];
    #pragma unroll
    for (int mi = 0; mi < 4; ++mi)
        #pragma unroll
        for (int ni = 0; ni < 4; ++ni)
            #pragma unroll
            for (int j = 0; j < 4; ++j) acc[mi][ni][j] = 0.f;

    float4 pb[4];
    float4 pa[4];
    uint4 qa[2];

    // ---- fetch + store chunk 0
    #pragma unroll
    for (int i = 0; i < 4; ++i) pb[i] = *(const float4*)(bP[i]);
    if (MODE == 0) {
        #pragma unroll
        for (int i = 0; i < 4; ++i) pa[i] = *(const float4*)(aP[i]);
    } else {
        #pragma unroll
        for (int i = 0; i < 2; ++i) qa[i] = *(const uint4*)(aPh[i]);
    }
    {
        __half* sA = smh;
        __half* sB = smh + ABUF_H;
        #pragma unroll
        for (int i = 0; i < 4; ++i) {
            uint2 u;
            u.x = h2bits(__floats2half2_rn(pb[i].x, pb[i].y));
            u.y = h2bits(__floats2half2_rn(pb[i].z, pb[i].w));
            *(uint2*)(sB + bOff[i]) = u;
        }
        if (MODE == 0) {
            #pragma unroll
            for (int i = 0; i < 4; ++i) {
                uint2 u;
                u.x = h2bits(__floats2half2_rn(pa[i].x, pa[i].y));
                u.y = h2bits(__floats2half2_rn(pa[i].z, pa[i].w));
                *(uint2*)(sA + aOff[i]) = u;
            }
        } else {
            #pragma unroll
            for (int i = 0; i < 2; ++i) *(uint4*)(sA + aOffH[i]) = qa[i];
        }
    }
    __syncthreads();

    for (int s = 0; s < NC; ++s) {
        int b = s & 1;
        if (s + 1 < NC) {
            #pragma unroll
            for (int i = 0; i < 4; ++i) pb[i] = *(const float4*)(bP[i] + (s + 1) * 32);
            if (MODE == 0) {
                #pragma unroll
                for (int i = 0; i < 4; ++i) pa[i] = *(const float4*)(aP[i] + (s + 1) * 32);
            } else {
                #pragma unroll
                for (int i = 0; i < 2; ++i) qa[i] = *(const uint4*)(aPh[i] + (s + 1) * 32);
            }
        }
        // ---- compute on buffer b
        uint32_t aA = aAddrBase + (uint32_t)(b * STAGE_H * 2);
        uint32_t bA = bAddrBase + (uint32_t)(b * STAGE_H * 2);
        #pragma unroll
        for (int ks = 0; ks < 2; ++ks) {
            uint32_t af[4][4];
            #pragma unroll
            for (int mi = 0; mi < 4; ++mi)
                ldsm4(aA + mi * (16 * TS * 2) + ks * 32, af[mi]);
            uint32_t bfr[8];
            #pragma unroll
            for (int ni2 = 0; ni2 < 2; ++ni2)
                ldsm4(bA + ni2 * (16 * TS * 2) + ks * 32, &bfr[ni2 * 4]);
            #pragma unroll
            for (int mi = 0; mi < 4; ++mi)
                #pragma unroll
                for (int ni = 0; ni < 4; ++ni)
                    mma_f16(acc[mi][ni], af[mi], &bfr[ni * 2]);
        }
        if (s + 1 < NC) {
            int nb = b ^ 1;
            __half* sA = smh + nb * STAGE_H;
            __half* sB = sA + ABUF_H;
            #pragma unroll
            for (int i = 0; i < 4; ++i) {
                uint2 u;
                u.x = h2bits(__floats2half2_rn(pb[i].x, pb[i].y));
                u.y = h2bits(__floats2half2_rn(pb[i].z, pb[i].w));
                *(uint2*)(sB + bOff[i]) = u;
            }
            if (MODE == 0) {
                #pragma unroll
                for (int i = 0; i < 4; ++i) {
                    uint2 u;
                    u.x = h2bits(__floats2half2_rn(pa[i].x, pa[i].y));
                    u.y = h2bits(__floats2half2_rn(pa[i].z, pa[i].w));
                    *(uint2*)(sA + aOff[i]) = u;
                }
            } else {
                #pragma unroll
                for (int i = 0; i < 2; ++i) *(uint4*)(sA + aOffH[i]) = qa[i];
            }
            __syncthreads();
        }
    }

    // ---- epilogue
    int r4 = lane >> 2, cc = (lane & 3) * 2;
    #pragma unroll
    for (int mi = 0; mi < 4; ++mi) {
        int row0 = m0 + mw + mi * 16 + r4;
        int row1 = row0 + 8;
        bool v0 = row0 < mEnd, v1 = row1 < mEnd;
        if (MODE == 0) {
            __half* C0 = g_h + (size_t)row0 * NTOT + n0;
            __half* C1 = g_h + (size_t)row1 * NTOT + n0;
            #pragma unroll
            for (int ni = 0; ni < 4; ++ni) {
                int col = nw + ni * 8 + cc;
                float bb0 = bias_s[col], bb1 = bias_s[col + 1];
                const float* d = acc[mi][ni];
                if (v0) {
                    __half2 h = __floats2half2_rn(fmaxf(d[0] + bb0, 0.f),
                                                  fmaxf(d[1] + bb1, 0.f));
                    *(__half2*)&C0[col] = h;
                }
                if (v1) {
                    __half2 h = __floats2half2_rn(fmaxf(d[2] + bb0, 0.f),
                                                  fmaxf(d[3] + bb1, 0.f));
                    *(__half2*)&C1[col] = h;
                }
            }
        } else {
            float w0 = 1.f, w1 = 1.f;
            if (v0) w0 = g_tw[g_perm[row0]];
            if (v1) w1 = g_tw[g_perm[row1]];
            float* C0 = g_contrib + (size_t)row0 * NTOT + n0;
            float* C1 = g_contrib + (size_t)row1 * NTOT + n0;
            #pragma unroll
            for (int ni = 0; ni < 4; ++ni) {
                int col = nw + ni * 8 + cc;
                float bb0 = bias_s[col], bb1 = bias_s[col + 1];
                const float* d = acc[mi][ni];
                if (v0) {
                    float2 o; o.x = (d[0] + bb0) * w0; o.y = (d[1] + bb1) * w0;
                    *(float2*)&C0[col] = o;
                }
                if (v1) {
                    float2 o; o.x = (d[2] + bb0) * w1; o.y = (d[3] + bb1) * w1;
                    *(float2*)&C1[col] = o;
                }
            }
        }
    }
}

// ---------------- combine ----------------------------------------------------
__global__ __launch_bounds__(256) void combine_kernel(float* __restrict__ out) {
    int idx = blockIdx.x * 256 + threadIdx.x;
    int tok = idx >> 8;
    int d4 = idx & 255;
    const float4* c0 = (const float4*)&g_contrib[(size_t)g_inv[tok * 2 + 0] * DOUT];
    const float4* c1 = (const float4*)&g_contrib[(size_t)g_inv[tok * 2 + 1] * DOUT];
    float4 a = c0[d4], b = c1[d4];
    float4 r;
    r.x = a.x + b.x; r.y = a.y + b.y; r.z = a.z + b.z; r.w = a.w + b.w;
    ((float4*)out)[idx] = r;
}

// ---------------- launch -----------------------------------------------------
extern "C" void kernel_launch(void* const* d_in, const int* in_sizes, int n_in,
                              void* d_out, int out_size) {
    const float* x  = (const float*)d_in[0];
    const float* gw = (const float*)d_in[1];
    const float* w1 = (const float*)d_in[2];
    const float* b1 = (const float*)d_in[3];
    const float* w2 = (const float*)d_in[4];
    const float* b2 = (const float*)d_in[5];
    float* out = (float*)d_out;

    init_kernel<<<1, 32>>>();
    gate_kernel<<<NB / 4, 128>>>(x, gw);
    prefix_kernel<<<1, 32>>>();
    scatter_kernel<<<(NB + 255) / 256, 256>>>();
    gemm_tc<DI, DH, 0><<<dim3(DH / 128, NSLOT / 128, NE), 256, GEMM_SMEM>>>(x, w1, b1);
    gemm_tc<DH, DOUT, 1><<<dim3(DOUT / 128, NSLOT / 128, NE), 256, GEMM_SMEM>>>(nullptr, w2, b2);
    combine_kernel<<<NB * (DOUT / 4) / 256, 256>>>(out);
}